// round 3
// baseline (speedup 1.0000x reference)
#include <cuda_runtime.h>
#include <cstdint>
#include <cstddef>

// Problem constants: images (32, 3, 256, 256) fp32
#define NIMG     32
#define KDIM     196608                 // 3*256*256 floats per image
#define CHUNK    256                    // floats of K handled per block
#define NCHUNK   (KDIM / CHUNK)         // 768 blocks
#define SROW     (CHUNK + 2)            // smem row stride (pad 2 floats -> bank = 2*row)
#define NTILE    36                     // upper-triangle 4x4 tiles of the 8x8 tile grid
#define NSLICE   8                      // k-slices per tile
#define THREADS_A (NTILE * NSLICE)      // 288 threads
#define NENT     (NTILE * 16)           // 576 partial entries per chunk

// Deterministic scratch: partial sums [entry][chunk]
__device__ float g_partial[NENT * NCHUNK];

__device__ __forceinline__ unsigned long long fsub2(unsigned long long a, unsigned long long b) {
    unsigned long long r;
    asm("sub.rn.f32x2 %0, %1, %2;" : "=l"(r) : "l"(a), "l"(b));
    return r;
}
__device__ __forceinline__ unsigned long long fadd2(unsigned long long a, unsigned long long b) {
    unsigned long long r;
    asm("add.rn.f32x2 %0, %1, %2;" : "=l"(r) : "l"(a), "l"(b));
    return r;
}

// Kernel A: per-chunk partial L1 sums for all unique 4x4 pair tiles.
__global__ __launch_bounds__(THREADS_A) void pairL1_partial(const float* __restrict__ images) {
    __shared__ float sdata[NIMG * SROW];   // 33,024 B

    const int tid   = threadIdx.x;
    const int chunk = blockIdx.x;

    // ---- Stage chunk of all 32 images into SMEM (float2, coalesced) ----
    for (int idx = tid; idx < NIMG * (CHUNK / 2); idx += THREADS_A) {
        const int row = idx >> 7;          // CHUNK/2 = 128 float2 per row
        const int c2  = idx & 127;
        const float2 v = *reinterpret_cast<const float2*>(
            images + (size_t)row * KDIM + (size_t)chunk * CHUNK + c2 * 2);
        *reinterpret_cast<float2*>(sdata + row * SROW + c2 * 2) = v;
    }
    __syncthreads();

    // ---- Pair-tile / k-slice assignment ----
    const int p     = tid % NTILE;     // pair-tile id (warp holds 32 distinct p)
    const int slice = tid / NTILE;     // k-slice 0..7 (32 floats each)

    int ti = 0, rem = p;               // decode upper-triangle tile (ti <= tj)
    while (rem >= 8 - ti) { rem -= 8 - ti; ++ti; }
    const int tj  = ti + rem;
    const int rot = (tj >= 4) ? 1 : 0; // bank-conflict stagger (rows 16 apart)

    const float* arow0 = sdata + (4 * ti) * SROW;
    const float* brow0 = sdata + (4 * tj) * SROW;

    unsigned long long acc[16];
    #pragma unroll
    for (int q = 0; q < 16; ++q) acc[q] = 0ull;

    #pragma unroll
    for (int l = 0; l < 16; ++l) {               // 16 f32x2 steps = 32 floats
        const int lr   = (l + rot) & 15;
        const int foff = slice * 32 + lr * 2;    // float offset within chunk

        unsigned long long A[4], Bv[4];
        #pragma unroll
        for (int m = 0; m < 4; ++m) {
            A[m]  = *reinterpret_cast<const unsigned long long*>(arow0 + m * SROW + foff);
            Bv[m] = *reinterpret_cast<const unsigned long long*>(brow0 + m * SROW + foff);
        }
        #pragma unroll
        for (int i = 0; i < 4; ++i) {
            #pragma unroll
            for (int j = 0; j < 4; ++j) {
                unsigned long long d = fsub2(A[i], Bv[j]) & 0x7FFFFFFF7FFFFFFFull;
                acc[i * 4 + j] = fadd2(acc[i * 4 + j], d);
            }
        }
    }
    __syncthreads();   // all SMEM reads done before we reuse sdata as scratch

    float* sred = sdata;  // [p][slice][16] = 4608 floats
    #pragma unroll
    for (int q = 0; q < 16; ++q) {
        const float lo = __uint_as_float((unsigned)(acc[q] & 0xffffffffull));
        const float hi = __uint_as_float((unsigned)(acc[q] >> 32));
        sred[(p * NSLICE + slice) * 16 + q] = lo + hi;
    }
    __syncthreads();

    for (int o = tid; o < NENT; o += THREADS_A) {
        const int po = o >> 4, e = o & 15;
        float s = 0.f;
        #pragma unroll
        for (int sl = 0; sl < NSLICE; ++sl) s += sred[(po * NSLICE + sl) * 16 + e];
        g_partial[o * NCHUNK + chunk] = s;
    }
}

// Kernel B: one warp per output pair; reduce 768 chunk partials, write output.
__global__ __launch_bounds__(256) void pairL1_finalize(float* __restrict__ out,
                                                       int attr_off, int write_idx) {
    const int warp = (blockIdx.x * blockDim.x + threadIdx.x) >> 5;
    const int lane = threadIdx.x & 31;
    if (warp >= NIMG * NIMG) return;

    const int x = warp >> 5;   // k // 32  (repeat)
    const int y = warp & 31;   // k %  32  (tile)

    int ti = x >> 2, tj = y >> 2, ii = x & 3, jj = y & 3;
    if (ti > tj) { int t = ti; ti = tj; tj = t; t = ii; ii = jj; jj = t; }
    const int p = 8 * ti - (ti * (ti - 1)) / 2 + (tj - ti);
    const int e = ii * 4 + jj;

    const float* base = g_partial + (size_t)(p * 16 + e) * NCHUNK;
    float s = 0.f;
    #pragma unroll
    for (int t = 0; t < NCHUNK / 32; ++t) s += base[lane + 32 * t];
    #pragma unroll
    for (int o = 16; o; o >>= 1) s += __shfl_xor_sync(0xffffffffu, s, o);

    if (lane == 0) {
        out[attr_off + warp] = s * (1.0f / (float)KDIM);
        if (write_idx) {
            out[warp]        = (float)x;   // edge_index row 0: repeat
            out[1024 + warp] = (float)y;   // edge_index row 1: tile
        }
    }
}

extern "C" void kernel_launch(void* const* d_in, const int* in_sizes, int n_in,
                              void* d_out, int out_size) {
    const float* images = (const float*)d_in[0];
    float* out = (float*)d_out;

    // Expected layout: [edge_index(2048), edge_attr(1024)] as float32.
    const int attr_off  = (out_size >= 3072) ? 2048 : 0;
    const int write_idx = (out_size >= 3072) ? 1 : 0;

    pairL1_partial<<<NCHUNK, THREADS_A>>>(images);
    pairL1_finalize<<<128, 256>>>(out, attr_off, write_idx);
}

// round 4
// speedup vs baseline: 1.0094x; 1.0094x over previous
#include <cuda_runtime.h>
#include <cstdint>
#include <cstddef>

// Problem constants: images (32, 3, 256, 256) fp32
#define NIMG     32
#define KDIM     196608                 // 3*256*256 floats per image
#define CHUNK    256                    // floats of K handled per block
#define NCHUNK   (KDIM / CHUNK)         // 768 blocks
#define SROW     (CHUNK + 2)            // smem row stride (pad 2 floats -> bank = 2*row)
#define NTILE    36                     // upper-triangle 4x4 tiles of the 8x8 tile grid
#define NSLICE   8                      // k-slices per tile
#define THREADS_A (NTILE * NSLICE)      // 288 threads
#define NENT     (NTILE * 16)           // 576 partial entries per chunk

// Deterministic scratch: partial sums [entry][chunk]
__device__ float g_partial[NENT * NCHUNK];

__device__ __forceinline__ unsigned long long fsub2(unsigned long long a, unsigned long long b) {
    unsigned long long r;
    asm("sub.rn.f32x2 %0, %1, %2;" : "=l"(r) : "l"(a), "l"(b));
    return r;
}
__device__ __forceinline__ unsigned long long fadd2(unsigned long long a, unsigned long long b) {
    unsigned long long r;
    asm("add.rn.f32x2 %0, %1, %2;" : "=l"(r) : "l"(a), "l"(b));
    return r;
}

// Kernel A: per-chunk partial L1 sums for all unique 4x4 pair tiles.
__global__ __launch_bounds__(THREADS_A) void pairL1_partial(const float* __restrict__ images) {
    __shared__ float sdata[NIMG * SROW];   // 33,024 B

    const int tid   = threadIdx.x;
    const int chunk = blockIdx.x;

    // ---- Stage chunk of all 32 images into SMEM (float2, coalesced) ----
    for (int idx = tid; idx < NIMG * (CHUNK / 2); idx += THREADS_A) {
        const int row = idx >> 7;          // CHUNK/2 = 128 float2 per row
        const int c2  = idx & 127;
        const float2 v = *reinterpret_cast<const float2*>(
            images + (size_t)row * KDIM + (size_t)chunk * CHUNK + c2 * 2);
        *reinterpret_cast<float2*>(sdata + row * SROW + c2 * 2) = v;
    }
    __syncthreads();

    // ---- Pair-tile / k-slice assignment ----
    const int p     = tid % NTILE;     // pair-tile id (warp holds 32 distinct p)
    const int slice = tid / NTILE;     // k-slice 0..7 (32 floats each)

    int ti = 0, rem = p;               // decode upper-triangle tile (ti <= tj)
    while (rem >= 8 - ti) { rem -= 8 - ti; ++ti; }
    const int tj  = ti + rem;
    const int rot = (tj >= 4) ? 1 : 0; // bank-conflict stagger (rows 16 apart)

    const float* arow0 = sdata + (4 * ti) * SROW;
    const float* brow0 = sdata + (4 * tj) * SROW;

    unsigned long long acc[16];
    #pragma unroll
    for (int q = 0; q < 16; ++q) acc[q] = 0ull;

    #pragma unroll
    for (int l = 0; l < 16; ++l) {               // 16 f32x2 steps = 32 floats
        const int lr   = (l + rot) & 15;
        const int foff = slice * 32 + lr * 2;    // float offset within chunk

        unsigned long long A[4], Bv[4];
        #pragma unroll
        for (int m = 0; m < 4; ++m) {
            A[m]  = *reinterpret_cast<const unsigned long long*>(arow0 + m * SROW + foff);
            Bv[m] = *reinterpret_cast<const unsigned long long*>(brow0 + m * SROW + foff);
        }
        #pragma unroll
        for (int i = 0; i < 4; ++i) {
            #pragma unroll
            for (int j = 0; j < 4; ++j) {
                unsigned long long d = fsub2(A[i], Bv[j]) & 0x7FFFFFFF7FFFFFFFull;
                acc[i * 4 + j] = fadd2(acc[i * 4 + j], d);
            }
        }
    }
    __syncthreads();   // all SMEM reads done before we reuse sdata as scratch

    float* sred = sdata;  // [p][slice][16] = 4608 floats
    #pragma unroll
    for (int q = 0; q < 16; ++q) {
        const float lo = __uint_as_float((unsigned)(acc[q] & 0xffffffffull));
        const float hi = __uint_as_float((unsigned)(acc[q] >> 32));
        sred[(p * NSLICE + slice) * 16 + q] = lo + hi;
    }
    __syncthreads();

    for (int o = tid; o < NENT; o += THREADS_A) {
        const int po = o >> 4, e = o & 15;
        float s = 0.f;
        #pragma unroll
        for (int sl = 0; sl < NSLICE; ++sl) s += sred[(po * NSLICE + sl) * 16 + e];
        g_partial[o * NCHUNK + chunk] = s;
    }
}

// Kernel B: one warp per output pair; reduce 768 chunk partials, write output.
__global__ __launch_bounds__(256) void pairL1_finalize(float* __restrict__ out,
                                                       int attr_off, int write_idx) {
    const int warp = (blockIdx.x * blockDim.x + threadIdx.x) >> 5;
    const int lane = threadIdx.x & 31;
    if (warp >= NIMG * NIMG) return;

    const int x = warp >> 5;   // k // 32  (repeat)
    const int y = warp & 31;   // k %  32  (tile)

    int ti = x >> 2, tj = y >> 2, ii = x & 3, jj = y & 3;
    if (ti > tj) { int t = ti; ti = tj; tj = t; t = ii; ii = jj; jj = t; }
    const int p = 8 * ti - (ti * (ti - 1)) / 2 + (tj - ti);
    const int e = ii * 4 + jj;

    const float* base = g_partial + (size_t)(p * 16 + e) * NCHUNK;
    float s = 0.f;
    #pragma unroll
    for (int t = 0; t < NCHUNK / 32; ++t) s += base[lane + 32 * t];
    #pragma unroll
    for (int o = 16; o; o >>= 1) s += __shfl_xor_sync(0xffffffffu, s, o);

    if (lane == 0) {
        out[attr_off + warp] = s * (1.0f / (float)KDIM);
        if (write_idx) {
            out[warp]        = (float)x;   // edge_index row 0: repeat
            out[1024 + warp] = (float)y;   // edge_index row 1: tile
        }
    }
}

extern "C" void kernel_launch(void* const* d_in, const int* in_sizes, int n_in,
                              void* d_out, int out_size) {
    const float* images = (const float*)d_in[0];
    float* out = (float*)d_out;

    // Expected layout: [edge_index(2048), edge_attr(1024)] as float32.
    const int attr_off  = (out_size >= 3072) ? 2048 : 0;
    const int write_idx = (out_size >= 3072) ? 1 : 0;

    pairL1_partial<<<NCHUNK, THREADS_A>>>(images);
    pairL1_finalize<<<128, 256>>>(out, attr_off, write_idx);
}